// round 13
// baseline (speedup 1.0000x reference)
#include <cuda_runtime.h>
#include <cuda_bf16.h>
#include <cstdint>
#include <cstddef>

#define BSZ       64
#define SEQLEN    512
#define NSTEP     255              // sequential LSE steps per direction
#define NT        48
#define NT2       (NT * NT)
#define START_TAG 46
#define END_TAG   47
#define TPS       384              // threads per stream (48 cols x 8 lanes)
#define TPB       (2 * TPS)        // two streams (fwd+bwd) per CTA
#define PD        4                // smem ring stages per stream
#define ROWPF     52               // fwd pad: banks (20*sub+j)%32 distinct
#define ROWPB     56               // bwd pad: banks (24*i+sub)%32 distinct; >=48 => no overlap
#define STGF      (NT * 56)        // stage stride floats (max of both layouts)
#define STGB      (STGF * 4)       // 10752 B/stage
#define RINGF     (PD * STGF)      // per-stream ring floats
#define NF4       (NT2 / 4)        // 576 float4 per tile
#define NCTA      BSZ              // 64 CTAs, one per batch

// Cross-CTA scratch.
__device__ float    g_fw[BSZ][NT + 1];   // [0..47]=v_fwd, [48]=C offset
__device__ float    g_bw[BSZ][NT + 1];
__device__ float    g_ts[BSZ];
__device__ unsigned g_cnt = 0;           // completion counter (reset each launch)

__device__ __forceinline__ void cpa16(uint32_t dst, const void* src) {
    asm volatile("cp.async.cg.shared.global [%0], [%1], 16;\n" :: "r"(dst), "l"(src));
}
__device__ __forceinline__ void cpa_commit() {
    asm volatile("cp.async.commit_group;\n" ::: "memory");
}
__device__ __forceinline__ void cpa_wait2() {
    asm volatile("cp.async.wait_group %0;\n" :: "n"(PD - 2) : "memory");
}
__device__ __forceinline__ void stream_bar(int id) {
    asm volatile("bar.sync %0, %1;" :: "r"(id), "r"(TPS) : "memory");
}

// 64 CTAs, one per batch; 768 threads = two 384-thread STREAMS.
// Stream 0 = forward recurrence over tiles 1..255 (+target path score),
// stream 1 = backward (beta) recurrence over tiles 511..256. Each stream has
// its own named barrier (bar.sync 1/2, 384) and its own 4-stage smem ring, so
// the streams drift out of phase and overlap complementary pipe bursts
// (LDS vs MUFU) on the same SM — attacking the phase-serialization seen in
// profiles (issue ~50%, no pipe >45%).
// Recurrence: v_k = log(sum exp(v_{k-1}+tile)) - (v_{k-1}[0]+4); true = v + C.
// The last CTA to finish performs the 64-batch LSE combine and writes out[0].
__global__ __launch_bounds__(TPB, 1) void crf_main(
    const float* __restrict__ tr,
    const void*  __restrict__ tgt,
    float*       __restrict__ out)
{
    extern __shared__ __align__(16) float dsm[];   // 2 * RINGF floats
    __shared__ float shr[2][2][NT];
    __shared__ float ts_w[TPS / 32];               // per-warp target-score slots
    __shared__ unsigned s_rank;

    const int tid = threadIdx.x;
    const int st  = (tid >= TPS);      // stream = direction
    const int t   = tid - st * TPS;    // tid within stream
    const int b   = blockIdx.x;
    const int dir = st;
    const int grp = t >> 3;            // fwd: column j | bwd: row i
    const int sub = t & 7;

    const float* __restrict__ tb = tr + (size_t)b * SEQLEN * NT2;

    const uint32_t tbase =
        (uint32_t)__cvta_generic_to_shared(dsm + st * RINGF);
    const int f1 = t;
    const int f2 = t + TPS;
    const int rowp = dir ? ROWPB : ROWPF;
    const uint32_t d1 = (uint32_t)((f1 / 12) * (rowp * 4) + (f1 % 12) * 16);
    const uint32_t d2 = (uint32_t)((f2 / 12) * (rowp * 4) + (f2 % 12) * 16);

    #define TILE_T(k) (dir ? (SEQLEN - 1 - (k)) : (k))

    if (t < NT) {
        shr[st][0][t] = dir
            ? tb[(size_t)(SEQLEN - 1) * NT2 + t * NT + END_TAG]  // beta_510
            : tb[START_TAG * NT + t];                             // forw_1
    }

    // ---- prologue: stage tiles k = 1 .. PD-1 (per stream) ----
    #pragma unroll
    for (int k = 1; k < PD; ++k) {
        uint32_t sb = tbase + (uint32_t)k * STGB;
        const char* s = (const char*)(tb + (size_t)TILE_T(k) * NT2);
        cpa16(sb + d1, s + (size_t)f1 * 16);
        if (t < NF4 - TPS) cpa16(sb + d2, s + (size_t)f2 * 16);
        cpa_commit();
    }

    // ---- target path score (stream 0 only; race-free per-warp slots) ----
    if (st == 0) {
        // int64 probe: if target is int64 (values < 2^31), every odd 32-bit
        // word of the tensor head is zero (L1-broadcast read).
        const int* t32h = (const int*)tgt;
        int is64 = __all_sync(0xffffffffu, t32h[2 * (t & 31) + 1] == 0);

        float ts = 0.0f;
        for (int s = t; s < SEQLEN; s += TPS) {
            int cur, prv;
            if (is64) {
                const long long* t64 = (const long long*)tgt + (size_t)b * SEQLEN;
                cur = (int)t64[s];
                prv = (s == 0) ? START_TAG : (int)t64[s - 1];
            } else {
                const int* t32 = (const int*)tgt + b * SEQLEN;
                cur = t32[s];
                prv = (s == 0) ? START_TAG : t32[s - 1];
            }
            ts += tb[(size_t)s * NT2 + prv * NT + cur];
        }
        #pragma unroll
        for (int m = 16; m; m >>= 1) ts += __shfl_xor_sync(0xffffffffu, ts, m);
        if ((t & 31) == 0) ts_w[t >> 5] = ts;
    }

    // ---- per-thread smem read offsets (conflict-free) ----
    // fwd: tile[(sub+8k)*52 + j]   banks (20*sub+j)%32 distinct in warp
    // bwd: tile[i*56 + sub + 8k]   banks (24*i+sub)%32 distinct in warp
    const int step8 = dir ? 8 : (8 * ROWPF);
    const int q0 = dir ? (grp * ROWPB + sub) : (sub * ROWPF + grp);
    const int q1 = q0 + step8;
    const int q2 = q0 + 2 * step8;
    const int q3 = q0 + 3 * step8;
    const int q4 = q0 + 4 * step8;
    const int q5 = q0 + 5 * step8;

    const float* ring = dsm + st * RINGF;
    float C = 0.0f;

    // ---- recurrence: k = 1 .. 255 (stream-local barriers only) ----
    for (int k = 1; k <= NSTEP; ++k) {
        cpa_wait2();          // this thread's stage-k copies complete
        stream_bar(st + 1);   // stream-wide visibility; stage k-1 readers done

        // Refill freed stage with tile k+PD-1 (post-barrier placement).
        if (k + PD - 1 <= NSTEP) {
            uint32_t sb = tbase + (uint32_t)((k + PD - 1) & (PD - 1)) * STGB;
            const char* s = (const char*)(tb + (size_t)TILE_T(k + PD - 1) * NT2);
            cpa16(sb + d1, s + (size_t)f1 * 16);
            if (t < NF4 - TPS) cpa16(sb + d2, s + (size_t)f2 * 16);
        }
        cpa_commit();

        const float* __restrict__ tl  = ring + (k & (PD - 1)) * STGF;
        const float* __restrict__ rin = shr[st][(k + 1) & 1];
        const float r0 = rin[sub];          // for sub==0 this is v[0]
        const float r1 = rin[sub +  8];
        const float r2 = rin[sub + 16];
        const float r3 = rin[sub + 24];
        const float r4 = rin[sub + 32];
        const float r5 = rin[sub + 40];

        float e0 = __expf(r0 + tl[q0]);
        float e1 = __expf(r1 + tl[q1]);
        float e2 = __expf(r2 + tl[q2]);
        float e3 = __expf(r3 + tl[q3]);
        float e4 = __expf(r4 + tl[q4]);
        float e5 = __expf(r5 + tl[q5]);

        float s = ((e0 + e1) + (e2 + e3)) + (e4 + e5);
        s += __shfl_xor_sync(0xffffffffu, s, 1);
        s += __shfl_xor_sync(0xffffffffu, s, 2);
        s += __shfl_xor_sync(0xffffffffu, s, 4);
        if (sub == 0) shr[st][k & 1][grp] = __logf(s) - (r0 + 4.0f);
        if (t == 0) C += r0 + 4.0f;   // accumulated normalization offset
    }

    stream_bar(st + 1);   // final shr[st][255&1] visible within stream
    {
        float* dst = st ? g_bw[b] : g_fw[b];
        if (t < NT) dst[t] = shr[st][NSTEP & 1][t];
        if (t == 0) {
            dst[NT] = C;
            if (st == 0) {
                float tss = 0.0f;
                #pragma unroll
                for (int w = 0; w < TPS / 32; ++w) tss += ts_w[w];
                g_ts[b] = tss;
            }
        }
    }

    // ---- last-CTA-done combine ----
    __threadfence();     // make this CTA's gmem stores visible gpu-wide
    __syncthreads();     // both streams done + fences before counter bump
    if (tid == 0) s_rank = atomicAdd(&g_cnt, 1u);
    __syncthreads();
    if (s_rank == NCTA - 1) {
        __threadfence(); // pair with writers' fences before reading g_*
        float loss = 0.0f;
        if (tid < BSZ) {
            const int bb = tid;
            float m = -1e30f;
            #pragma unroll 4
            for (int i = 0; i < NT; ++i) m = fmaxf(m, g_fw[bb][i] + g_bw[bb][i]);
            float s = 0.0f;
            #pragma unroll 4
            for (int i = 0; i < NT; ++i) s += __expf(g_fw[bb][i] + g_bw[bb][i] - m);
            float F = __logf(s) + m + g_fw[bb][NT] + g_bw[bb][NT];
            loss = F - g_ts[bb];
        }
        #pragma unroll
        for (int o = 16; o; o >>= 1) loss += __shfl_xor_sync(0xffffffffu, loss, o);
        if (tid == 0 || tid == 32) shr[0][0][tid >> 5] = loss;  // reuse smem
        __syncthreads();
        if (tid == 0) {
            out[0] = (shr[0][0][0] + shr[0][0][1]) * (1.0f / (float)BSZ);
            g_cnt = 0;   // reset for next graph replay
        }
    }
    #undef TILE_T
}

extern "C" void kernel_launch(void* const* d_in, const int* in_sizes, int n_in,
                              void* d_out, int out_size) {
    const void* trans = d_in[0];
    const void* tgt   = d_in[1];
    if (n_in >= 2 && in_sizes[0] < in_sizes[1]) {
        trans = d_in[1];
        tgt   = d_in[0];
    }
    const int dyn = 2 * RINGF * 4;   // 86016 B: two 4-stage rings
    cudaFuncSetAttribute(crf_main, cudaFuncAttributeMaxDynamicSharedMemorySize, dyn);
    crf_main<<<NCTA, TPB, dyn>>>((const float*)trans, tgt, (float*)d_out);
}

// round 15
// speedup vs baseline: 1.3911x; 1.3911x over previous
#include <cuda_runtime.h>
#include <cuda_bf16.h>
#include <cstdint>
#include <cstddef>

#define BSZ       64
#define SEQLEN    512
#define NSTEP     255              // sequential LSE steps per direction
#define NT        48
#define NT2       (NT * NT)
#define START_TAG 46
#define END_TAG   47
#define TPB       384              // 48 x 8
#define PD        4                // smem ring stages (power of 2, static)
#define ROWPF     52               // fwd pad: banks (20*sub+j)%32 distinct
#define ROWPB     56               // bwd pad: banks (24*i+sub)%32 distinct; >=48 => no overlap
#define STGF      (NT * 56)        // stage stride floats (max of both layouts)
#define STGB      (STGF * 4)       // 10752 B/stage; 4 stages = 43008 B static
#define NF4       (NT2 / 4)        // 576 float4 per tile
#define NCTA      (2 * BSZ)        // 128

#define INV_LN2   1.4426950408889634f
#define LN2       0.6931471805599453f
#define OFF2      5.770780163555854f   // 4 / ln2

// Cross-CTA scratch.
__device__ float    g_fw[BSZ][NT + 1];   // [0..47]=v2_fwd (base-2), [48]=C2 offset
__device__ float    g_bw[BSZ][NT + 1];
__device__ float    g_ts[BSZ];
__device__ unsigned g_cnt = 0;           // completion counter (reset each launch)

__device__ __forceinline__ void cpa16(uint32_t dst, const void* src) {
    asm volatile("cp.async.cg.shared.global [%0], [%1], 16;\n" :: "r"(dst), "l"(src));
}
__device__ __forceinline__ void cpa_commit() {
    asm volatile("cp.async.commit_group;\n" ::: "memory");
}
__device__ __forceinline__ void cpa_wait2() {
    asm volatile("cp.async.wait_group %0;\n" :: "n"(PD - 2) : "memory");
}
__device__ __forceinline__ float ex2f(float x) {
    float y;
    asm("ex2.approx.ftz.f32 %0, %1;" : "=f"(y) : "f"(x));
    return y;
}

// 128 CTAs: blockIdx.x = 2*b + dir. dir=0: forward over tiles 1..255 (+target
// score). dir=1: backward (beta) over tiles 511..256. 48-wide LSE recurrence
// carried in BASE-2 log space: per element e = EX2(fma(tile, 1/ln2, v2)) —
// one FFMA+EX2 instead of FADD+FMUL+EX2 — and the output is a bare LG2.
// Normalization: v2_k = log2(s) - (v2_{k-1}[0] + 4/ln2); true value =
// (v2 + C2) * ln2. Tiles stream through a 4-stage padded static-smem ring via
// coalesced 16B cp.async (refill post-barrier — proven placement). The last
// CTA to finish performs the 64-batch combine and writes out[0].
__global__ __launch_bounds__(TPB, 1) void crf_main(
    const float* __restrict__ tr,
    const void*  __restrict__ tgt,
    float*       __restrict__ out)
{
    __shared__ __align__(16) float tile[PD][STGF];
    __shared__ float shr[2][NT];
    __shared__ float ts_w[TPB / 32];    // per-warp target-score slots
    __shared__ unsigned s_rank;

    const int tid = threadIdx.x;
    const int b   = blockIdx.x >> 1;
    const int dir = blockIdx.x & 1;
    const int grp = tid >> 3;   // fwd: column j | bwd: row i
    const int sub = tid & 7;

    const float* __restrict__ tb = tr + (size_t)b * SEQLEN * NT2;

    const uint32_t tbase = (uint32_t)__cvta_generic_to_shared(&tile[0][0]);
    const int f1 = tid;
    const int f2 = tid + TPB;
    const int rowp = dir ? ROWPB : ROWPF;
    const uint32_t d1 = (uint32_t)((f1 / 12) * (rowp * 4) + (f1 % 12) * 16);
    const uint32_t d2 = (uint32_t)((f2 / 12) * (rowp * 4) + (f2 % 12) * 16);

    #define TILE_T(k) (dir ? (SEQLEN - 1 - (k)) : (k))

    if (tid < NT) {
        // init in base-2 units
        shr[0][tid] = INV_LN2 * (dir
            ? tb[(size_t)(SEQLEN - 1) * NT2 + tid * NT + END_TAG]  // beta_510
            : tb[START_TAG * NT + tid]);                            // forw_1
    }

    // ---- prologue: stage tiles k = 1 .. PD-1 ----
    #pragma unroll
    for (int k = 1; k < PD; ++k) {
        uint32_t sb = tbase + (uint32_t)k * STGB;
        const char* s = (const char*)(tb + (size_t)TILE_T(k) * NT2);
        cpa16(sb + d1, s + (size_t)f1 * 16);
        if (tid < NF4 - TPB) cpa16(sb + d2, s + (size_t)f2 * 16);
        cpa_commit();
    }

    // ---- target path score (fwd CTA only; race-free per-warp slots) ----
    if (dir == 0) {
        // int64 probe: if target is int64 (values < 2^31), every odd 32-bit
        // word of the tensor head is zero (L1-broadcast read).
        const int* t32h = (const int*)tgt;
        int is64 = __all_sync(0xffffffffu, t32h[2 * (tid & 31) + 1] == 0);

        float ts = 0.0f;
        for (int s = tid; s < SEQLEN; s += TPB) {
            int cur, prv;
            if (is64) {
                const long long* t64 = (const long long*)tgt + (size_t)b * SEQLEN;
                cur = (int)t64[s];
                prv = (s == 0) ? START_TAG : (int)t64[s - 1];
            } else {
                const int* t32 = (const int*)tgt + b * SEQLEN;
                cur = t32[s];
                prv = (s == 0) ? START_TAG : t32[s - 1];
            }
            ts += tb[(size_t)s * NT2 + prv * NT + cur];
        }
        #pragma unroll
        for (int m = 16; m; m >>= 1) ts += __shfl_xor_sync(0xffffffffu, ts, m);
        if ((tid & 31) == 0) ts_w[tid >> 5] = ts;
    }

    // ---- per-thread smem read offsets (conflict-free) ----
    // fwd: tile[(sub+8k)*52 + j]   banks (20*sub+j)%32 distinct in warp
    // bwd: tile[i*56 + sub + 8k]   banks (24*i+sub)%32 distinct in warp
    const int step8 = dir ? 8 : (8 * ROWPF);
    const int q0 = dir ? (grp * ROWPB + sub) : (sub * ROWPF + grp);
    const int q1 = q0 + step8;
    const int q2 = q0 + 2 * step8;
    const int q3 = q0 + 3 * step8;
    const int q4 = q0 + 4 * step8;
    const int q5 = q0 + 5 * step8;

    // ---- strength-reduced loop pointers ----
    const long dstep = dir ? -(long)NT2 : (long)NT2;
    const float* src_rf = tb + (size_t)TILE_T(PD) * NT2;   // refill source, step 1
    uint32_t sb_rf = tbase;                                // stage PD&3 == 0
    const float* tlp = &tile[1][0];                        // consume stage, step 1

    float C2 = 0.0f;

    // ---- recurrence: k = 1 .. 255 ----
    for (int k = 1; k <= NSTEP; ++k) {
        cpa_wait2();         // stage k copies complete (this thread)
        __syncthreads();     // cross-thread visibility; stage k-1 readers done

        // Refill freed stage with tile k+PD-1 (post-barrier placement).
        if (k <= NSTEP - (PD - 1)) {
            const char* s = (const char*)src_rf;
            cpa16(sb_rf + d1, s + (size_t)f1 * 16);
            if (tid < NF4 - TPB) cpa16(sb_rf + d2, s + (size_t)f2 * 16);
        }
        cpa_commit();
        src_rf += dstep;
        sb_rf += STGB;
        if (sb_rf == tbase + PD * STGB) sb_rf = tbase;

        const float* __restrict__ tl = tlp;
        tlp += STGF;
        if (tlp == &tile[0][0] + PD * STGF) tlp = &tile[0][0];

        const float* __restrict__ rin = &shr[(k + 1) & 1][0];
        const float r0 = rin[sub];          // for sub==0 this is v2[0]
        const float r1 = rin[sub +  8];
        const float r2 = rin[sub + 16];
        const float r3 = rin[sub + 24];
        const float r4 = rin[sub + 32];
        const float r5 = rin[sub + 40];

        float e0 = ex2f(fmaf(tl[q0], INV_LN2, r0));
        float e1 = ex2f(fmaf(tl[q1], INV_LN2, r1));
        float e2 = ex2f(fmaf(tl[q2], INV_LN2, r2));
        float e3 = ex2f(fmaf(tl[q3], INV_LN2, r3));
        float e4 = ex2f(fmaf(tl[q4], INV_LN2, r4));
        float e5 = ex2f(fmaf(tl[q5], INV_LN2, r5));

        float s = ((e0 + e1) + (e2 + e3)) + (e4 + e5);
        s += __shfl_xor_sync(0xffffffffu, s, 1);
        s += __shfl_xor_sync(0xffffffffu, s, 2);
        s += __shfl_xor_sync(0xffffffffu, s, 4);
        if (sub == 0) shr[k & 1][grp] = __log2f(s) - (r0 + OFF2);
        if (tid == 0) C2 += r0 + OFF2;   // accumulated base-2 offset
    }

    __syncthreads();
    {
        float* dst = dir ? g_bw[b] : g_fw[b];
        if (tid < NT) dst[tid] = shr[NSTEP & 1][tid];
        if (tid == 0) {
            dst[NT] = C2;
            if (dir == 0) {
                float tss = 0.0f;
                #pragma unroll
                for (int w = 0; w < TPB / 32; ++w) tss += ts_w[w];
                g_ts[b] = tss;
            }
        }
    }

    // ---- last-CTA-done combine ----
    __threadfence();     // make this CTA's gmem stores visible gpu-wide
    __syncthreads();     // all fences done before the counter bump
    if (tid == 0) s_rank = atomicAdd(&g_cnt, 1u);
    __syncthreads();
    if (s_rank == NCTA - 1) {
        __threadfence(); // pair with writers' fences before reading g_*
        float loss = 0.0f;
        if (tid < BSZ) {
            const int bb = tid;
            float m = -1e30f;
            #pragma unroll 4
            for (int i = 0; i < NT; ++i) m = fmaxf(m, g_fw[bb][i] + g_bw[bb][i]);
            float s = 0.0f;
            #pragma unroll 4
            for (int i = 0; i < NT; ++i) s += ex2f(g_fw[bb][i] + g_bw[bb][i] - m);
            // back to natural log units
            float F = LN2 * (__log2f(s) + m + g_fw[bb][NT] + g_bw[bb][NT]);
            loss = F - g_ts[bb];
        }
        #pragma unroll
        for (int o = 16; o; o >>= 1) loss += __shfl_xor_sync(0xffffffffu, loss, o);
        if (tid == 0 || tid == 32) shr[0][tid >> 5] = loss;  // reuse smem
        __syncthreads();
        if (tid == 0) {
            out[0] = (shr[0][0] + shr[0][1]) * (1.0f / (float)BSZ);
            g_cnt = 0;   // reset for next graph replay
        }
    }
    #undef TILE_T
}

extern "C" void kernel_launch(void* const* d_in, const int* in_sizes, int n_in,
                              void* d_out, int out_size) {
    const void* trans = d_in[0];
    const void* tgt   = d_in[1];
    if (n_in >= 2 && in_sizes[0] < in_sizes[1]) {
        trans = d_in[1];
        tgt   = d_in[0];
    }
    crf_main<<<NCTA, TPB>>>((const float*)trans, tgt, (float*)d_out);
}